// round 4
// baseline (speedup 1.0000x reference)
#include <cuda_runtime.h>
#include <cstdint>
#include <cstdio>
#include <cstring>
#include <math.h>

#define NW     8
#define QDIM   256
#define NRAND  20
#define NGATES 28       // 20 random + 8 final RX
#define TPB    256
#define BSAMP  64       // samples per block
#define NSAMP  65536    // 64*1024

struct OpsParam { int kind[NGATES]; int wa[NGATES]; int wb[NGATES]; };

// W matrix, phase-folded, layout B[j][2*i+0]=Re W_ij, B[j][2*i+1]=Im W_ij
__device__ float g_B[QDIM * 512];

// ---------------------------------------------------------------------------
// Setup kernel: build column j of U = G28...G1, fold phase (-i)^popc(j).
// One block per column j, 128 threads, state in smem.
// ---------------------------------------------------------------------------
__global__ void build_W_kernel(const float* __restrict__ rx_params,
                               const float* __restrict__ random_params,
                               OpsParam ops) {
    __shared__ float2 st[QDIM];
    const int j   = blockIdx.x;
    const int tid = threadIdx.x;   // 0..127

    for (int idx = tid; idx < QDIM; idx += 128)
        st[idx] = make_float2(idx == j ? 1.0f : 0.0f, 0.0f);
    __syncthreads();

    for (int p = 0; p < NGATES; p++) {
        int g = ops.kind[p];
        if (g == 3) {
            // CNOT: control wire wa, target wire wb
            int cm = 1 << (7 - ops.wa[p]);
            int tm = 1 << (7 - ops.wb[p]);
            for (int idx = tid; idx < QDIM; idx += 128) {
                if ((idx & cm) && !(idx & tm)) {
                    float2 t0 = st[idx];
                    st[idx] = st[idx | tm];
                    st[idx | tm] = t0;
                }
            }
        } else {
            float theta = (p < NRAND) ? random_params[p] : rx_params[p - NRAND];
            float h = 0.5f * theta;
            float c = cosf(h), s = sinf(h);
            int m  = 1 << (7 - ops.wa[p]);
            int t  = tid;                       // 128 pairs cover all 256 indices
            int j0 = ((t & ~(m - 1)) << 1) | (t & (m - 1));
            int j1 = j0 | m;
            float2 v0 = st[j0], v1 = st[j1], n0, n1;
            if (g == 0) {          // RX
                n0 = make_float2(c * v0.x + s * v1.y, c * v0.y - s * v1.x);
                n1 = make_float2(c * v1.x + s * v0.y, c * v1.y - s * v0.x);
            } else if (g == 1) {   // RY
                n0 = make_float2(c * v0.x - s * v1.x, c * v0.y - s * v1.y);
                n1 = make_float2(s * v0.x + c * v1.x, s * v0.y + c * v1.y);
            } else {               // RZ
                n0 = make_float2(c * v0.x + s * v0.y, c * v0.y - s * v0.x);
                n1 = make_float2(c * v1.x - s * v1.y, c * v1.y + s * v1.x);
            }
            st[j0] = n0;
            st[j1] = n1;
        }
        __syncthreads();
    }

    // fold phase (-i)^popc(j) into this column, write transposed/interleaved
    int pc = __popc(j) & 3;
    for (int i = tid; i < QDIM; i += 128) {
        float2 v = st[i];
        float re, im;
        if (pc == 0)      { re =  v.x; im =  v.y; }
        else if (pc == 1) { re =  v.y; im = -v.x; }
        else if (pc == 2) { re = -v.x; im = -v.y; }
        else              { re = -v.y; im =  v.x; }
        g_B[j * 512 + 2 * i]     = re;
        g_B[j * 512 + 2 * i + 1] = im;
    }
}

// ---------------------------------------------------------------------------
// Main kernel: per block, 64 samples.
// ---------------------------------------------------------------------------
__global__ __launch_bounds__(TPB, 1)
void qsim_kernel(const float* __restrict__ x, float* __restrict__ out) {
    extern __shared__ float sm[];
    float* R  = sm;                 // [256][64]  = 64 KB
    float* Bs = sm + QDIM * BSAMP;  // [64][256]  = 64 KB
    const int tid = threadIdx.x;
    const int b   = blockIdx.x;
    const int smp0 = b * BSAMP;

    // ---- Phase 1: build R (4 threads per sample) ----
    {
        int s = tid >> 2, q = tid & 3;
        const float* xp = x + (size_t)(smp0 + s) * 8;
        float fc[8], fs[8];
#pragma unroll
        for (int w = 0; w < 8; w++) {
            float h = 0.5f * xp[w];
            fc[w] = cosf(h);
            fs[w] = sinf(h);
        }
        float f01 = ((q & 2) ? fs[0] : fc[0]) * ((q & 1) ? fs[1] : fc[1]);
#pragma unroll
        for (int jj = 0; jj < 64; jj++) {
            float r = f01;
            r *= (jj & 32) ? fs[2] : fc[2];
            r *= (jj & 16) ? fs[3] : fc[3];
            r *= (jj &  8) ? fs[4] : fc[4];
            r *= (jj &  4) ? fs[5] : fc[5];
            r *= (jj &  2) ? fs[6] : fc[6];
            r *= (jj &  1) ? fs[7] : fc[7];
            R[(q * 64 + jj) * BSAMP + s] = r;
        }
    }
    __syncthreads();

    const int ty = tid >> 5;   // 0..7  (warp id, m-dim)
    const int tx = tid & 31;   // lane  (n-dim)

    float outacc[8][8];
#pragma unroll
    for (int i = 0; i < 8; i++)
#pragma unroll
        for (int k = 0; k < 8; k++) outacc[i][k] = 0.0f;

    for (int nc = 0; nc < 2; nc++) {          // two 256-col chunks of 512
        float acc[2][2][4][4];
#pragma unroll
        for (int a0 = 0; a0 < 2; a0++)
#pragma unroll
            for (int a1 = 0; a1 < 2; a1++)
#pragma unroll
                for (int a2 = 0; a2 < 4; a2++)
#pragma unroll
                    for (int a3 = 0; a3 < 4; a3++) acc[a0][a1][a2][a3] = 0.0f;

        for (int kc = 0; kc < 4; kc++) {      // four 64-row K chunks
            const float4* Bg = (const float4*)g_B;  // row stride 128 float4
#pragma unroll
            for (int it = 0; it < 16; it++) {
                int f   = tid + it * 256;     // 0..4095 float4 slots
                int row = f >> 6, c4 = f & 63;
                ((float4*)Bs)[f] = Bg[(size_t)(kc * 64 + row) * 128 + nc * 64 + c4];
            }
            __syncthreads();

#pragma unroll 8
            for (int kk = 0; kk < 64; kk++) {
                const float* Rrow = R + (kc * 64 + kk) * BSAMP;
                float4 a0 = *(const float4*)(Rrow + ty * 4);
                float4 a1 = *(const float4*)(Rrow + 32 + ty * 4);
                const float* Brow = Bs + kk * 256;
                float4 b0 = *(const float4*)(Brow + tx * 4);
                float4 b1 = *(const float4*)(Brow + 128 + tx * 4);
                float am[2][4] = {{a0.x, a0.y, a0.z, a0.w}, {a1.x, a1.y, a1.z, a1.w}};
                float bn[2][4] = {{b0.x, b0.y, b0.z, b0.w}, {b1.x, b1.y, b1.z, b1.w}};
#pragma unroll
                for (int mh = 0; mh < 2; mh++)
#pragma unroll
                    for (int nh = 0; nh < 2; nh++)
#pragma unroll
                        for (int mi = 0; mi < 4; mi++)
#pragma unroll
                            for (int ni = 0; ni < 4; ni++)
                                acc[mh][nh][mi][ni] += am[mh][mi] * bn[nh][ni];
            }
            __syncthreads();
        }

        // amplitude i = nc*128 + nh*64 + tx*2 + jhalf
#pragma unroll
        for (int mh = 0; mh < 2; mh++)
#pragma unroll
            for (int nh = 0; nh < 2; nh++)
#pragma unroll
                for (int mi = 0; mi < 4; mi++) {
                    float cx = acc[mh][nh][mi][0], cy = acc[mh][nh][mi][1];
                    float cz = acc[mh][nh][mi][2], cw = acc[mh][nh][mi][3];
                    float p0 = cx * cx + cy * cy;
                    float p1 = cz * cz + cw * cw;
                    float P = p0 + p1, Q = p0 - p1;
                    int mloc = mh * 4 + mi;
                    outacc[mloc][0] += nc ? -P : P;
                    outacc[mloc][1] += nh ? -P : P;
                    outacc[mloc][7] += Q;
#pragma unroll
                    for (int k = 2; k <= 6; k++)
                        outacc[mloc][k] += ((tx >> (6 - k)) & 1) ? -P : P;
                }
    }

#pragma unroll
    for (int mloc = 0; mloc < 8; mloc++) {
#pragma unroll
        for (int k = 0; k < 8; k++) {
            float v = outacc[mloc][k];
            v += __shfl_xor_sync(0xffffffffu, v, 16);
            v += __shfl_xor_sync(0xffffffffu, v, 8);
            v += __shfl_xor_sync(0xffffffffu, v, 4);
            v += __shfl_xor_sync(0xffffffffu, v, 2);
            v += __shfl_xor_sync(0xffffffffu, v, 1);
            if (tx == 0) {
                int m = (mloc >> 2) * 32 + ty * 4 + (mloc & 3);
                out[(size_t)(smp0 + m) * 8 + k] = v;
            }
        }
    }
}

// ---------------------------------------------------------------------------
// GATE_OPS via the exact reference mechanism: run numpy in a subprocess
// (same container the reference ran in). Bit-exact by construction.
// ---------------------------------------------------------------------------
static const char* PY_SNIPPET =
    "import numpy as np\n"
    "r = np.random.default_rng(42)\n"
    "for _ in range(20):\n"
    "    g = int(r.integers(0, 4))\n"
    "    if g == 3:\n"
    "        c, t = r.choice(8, size=2, replace=False)\n"
    "        print(3, int(c), int(t))\n"
    "    else:\n"
    "        print(g, int(r.integers(0, 8)), -1)\n";

static bool compute_gate_ops_python(OpsParam& ops, const char* interp) {
    char cmd[2048];
    snprintf(cmd, sizeof(cmd), "%s -c '%s' 2>/dev/null", interp, PY_SNIPPET);
    FILE* f = popen(cmd, "r");
    if (!f) return false;
    int n = 0;
    while (n < NRAND) {
        int g, a, b;
        if (fscanf(f, "%d %d %d", &g, &a, &b) != 3) break;
        if (g < 0 || g > 3 || a < 0 || a > 7 || (g == 3 && (b < 0 || b > 7))) break;
        ops.kind[n] = g; ops.wa[n] = a; ops.wb[n] = b;
        n++;
    }
    int rc = pclose(f);
    (void)rc;
    return n == NRAND;
}

// ---------------------------------------------------------------------------
// Fallback: host-side replication of np.random.default_rng(42).
// ---------------------------------------------------------------------------
namespace nprng {

struct PCG64 { __uint128_t state, inc; int has32; uint32_t buf32; };

static const __uint128_t PCG_MULT =
    (((__uint128_t)2549297995355413924ULL) << 64) | 4865540595714422341ULL;

static uint64_t next64(PCG64& r) {
    r.state = r.state * PCG_MULT + r.inc;
    uint64_t hi = (uint64_t)(r.state >> 64), lo = (uint64_t)r.state;
    uint64_t xv = hi ^ lo;
    unsigned rot = (unsigned)(r.state >> 122);
    return (xv >> rot) | (xv << ((64u - rot) & 63u));
}

static uint32_t next32(PCG64& r) {
    if (r.has32) { r.has32 = 0; return r.buf32; }
    uint64_t v = next64(r);
    r.has32 = 1;
    r.buf32 = (uint32_t)(v >> 32);
    return (uint32_t)v;
}

static void seedseq42(uint64_t out[4]) {
    const uint32_t XSH = 16;
    uint32_t pool[4];
    uint32_t hc = 0x43b0d7e5u;
    auto hashmix = [&](uint32_t v) {
        v ^= hc; hc *= 0x931e8875u; v *= hc; v ^= v >> XSH; return v;
    };
    auto mixf = [&](uint32_t xx, uint32_t yy) {
        uint32_t rr = (xx * 0xca01f9ddu) ^ (yy * 0x4973f715u);
        rr ^= rr >> XSH; return rr;
    };
    pool[0] = hashmix(42u);
    pool[1] = hashmix(0u);
    pool[2] = hashmix(0u);
    pool[3] = hashmix(0u);
    for (int src = 0; src < 4; src++)
        for (int dst = 0; dst < 4; dst++)
            if (src != dst) pool[dst] = mixf(pool[dst], hashmix(pool[src]));
    uint32_t hb = 0x8b51f9ddu;
    uint32_t w[8];
    for (int i = 0; i < 8; i++) {
        uint32_t v = pool[i & 3];
        v ^= hb; hb *= 0x58f38dedu; v *= hb; v ^= v >> XSH;
        w[i] = v;
    }
    for (int k = 0; k < 4; k++)
        out[k] = (uint64_t)w[2 * k] | ((uint64_t)w[2 * k + 1] << 32);
}

static void init42(PCG64& r) {
    uint64_t s4[4];
    seedseq42(s4);
    __uint128_t initstate = (((__uint128_t)s4[0]) << 64) | s4[1];
    __uint128_t initseq   = (((__uint128_t)s4[2]) << 64) | s4[3];
    r.state = 0;
    r.inc   = (initseq << 1) | 1;
    r.state = r.state * PCG_MULT + r.inc;
    r.state += initstate;
    r.state = r.state * PCG_MULT + r.inc;
    r.has32 = 0;
    r.buf32 = 0;
}

static uint64_t lemire32(PCG64& r, uint32_t rng) {
    uint32_t rng_excl = rng + 1;
    uint64_t m = (uint64_t)next32(r) * (uint64_t)rng_excl;
    uint32_t leftover = (uint32_t)m;
    if (leftover < rng_excl) {
        uint32_t threshold = (uint32_t)((0xFFFFFFFFu - rng) % rng_excl);
        while (leftover < threshold) {
            m = (uint64_t)next32(r) * (uint64_t)rng_excl;
            leftover = (uint32_t)m;
        }
    }
    return (uint64_t)(m >> 32);
}

} // namespace nprng

static void compute_gate_ops_cpp(OpsParam& ops) {
    nprng::PCG64 r;
    nprng::init42(r);
    for (int p = 0; p < NRAND; p++) {
        int g = (int)nprng::lemire32(r, 3);
        if (g == 3) {
            uint64_t v6 = nprng::lemire32(r, 6);
            uint64_t v7 = nprng::lemire32(r, 7);
            uint64_t i0 = v6;
            uint64_t i1 = (v7 == v6) ? 7 : v7;
            uint64_t js = nprng::lemire32(r, 1);   // _shuffle_int -> 32-bit Lemire
            if (js == 0) { uint64_t t = i0; i0 = i1; i1 = t; }
            ops.kind[p] = 3;
            ops.wa[p] = (int)i0;
            ops.wb[p] = (int)i1;
        } else {
            ops.kind[p] = g;
            ops.wa[p] = (int)nprng::lemire32(r, 7);
            ops.wb[p] = -1;
        }
    }
}

extern "C" void kernel_launch(void* const* d_in, const int* in_sizes, int n_in,
                              void* d_out, int out_size) {
    // Select input pointers by element count (robust to metadata ordering):
    // x: 524288 elems, rx_params: 8, random_params: 20.
    const float* x  = nullptr;
    const float* rx = nullptr;
    const float* rp = nullptr;
    for (int i = 0; i < n_in; i++) {
        if (in_sizes[i] == 8)       rx = (const float*)d_in[i];
        else if (in_sizes[i] == 20) rp = (const float*)d_in[i];
        else                        x  = (const float*)d_in[i];
    }
    if (!x)  x  = (const float*)d_in[0];
    if (!rx) rx = (const float*)d_in[1];
    if (!rp) rp = (const float*)d_in[2];
    float* out = (float*)d_out;
    (void)out_size;

    OpsParam ops;
    bool ok = compute_gate_ops_python(ops, "python3");
    if (!ok) ok = compute_gate_ops_python(ops, "python");
    if (!ok) {
        fprintf(stderr, "[qsim] python GATE_OPS derivation FAILED -> C++ fallback\n");
        compute_gate_ops_cpp(ops);
    }
    fprintf(stderr, "[qsim] ops(src=%s):", ok ? "python" : "cpp");
    for (int p = 0; p < NRAND; p++)
        fprintf(stderr, " (%d,%d,%d)", ops.kind[p], ops.wa[p], ops.wb[p]);
    fprintf(stderr, "\n");
    fflush(stderr);

    // Sanity: add the 8 final RX gates
    for (int w = 0; w < 8; w++) {
        ops.kind[NRAND + w] = 0;
        ops.wa[NRAND + w] = w;
        ops.wb[NRAND + w] = -1;
    }

    cudaFuncSetAttribute(qsim_kernel, cudaFuncAttributeMaxDynamicSharedMemorySize,
                         (QDIM * BSAMP + 64 * 256) * sizeof(float));

    build_W_kernel<<<QDIM, 128>>>(rx, rp, ops);
    qsim_kernel<<<NSAMP / BSAMP, TPB, (QDIM * BSAMP + 64 * 256) * sizeof(float)>>>(x, out);
}

// round 5
// speedup vs baseline: 1.0848x; 1.0848x over previous
#include <cuda_runtime.h>
#include <cstdint>
#include <cstdio>
#include <cstring>
#include <math.h>

#define NW     8
#define QDIM   256
#define NRAND  20
#define NGATES 28       // 20 random + 8 final RX
#define TPB    256
#define BSAMP  64       // samples per block
#define NSAMP  65536    // 64*1024

struct OpsParam { int kind[NGATES]; int wa[NGATES]; int wb[NGATES]; };

// W matrix, phase-folded, layout B[j][2*i+0]=Re W_ij, B[j][2*i+1]=Im W_ij
__device__ float g_B[QDIM * 512];

// ---------------------------------------------------------------------------
// Packed f32x2 helpers (Blackwell FFMA2 path — only reachable via PTX)
// ---------------------------------------------------------------------------
__device__ __forceinline__ void ffma2(unsigned long long& d,
                                      unsigned long long a,
                                      unsigned long long b) {
    asm("fma.rn.f32x2 %0, %1, %2, %0;" : "+l"(d) : "l"(a), "l"(b));
}
__device__ __forceinline__ unsigned long long dup2(float a) {
    unsigned long long r;
    unsigned int u = __float_as_uint(a);
    asm("mov.b64 %0, {%1, %1};" : "=l"(r) : "r"(u));
    return r;
}
__device__ __forceinline__ void unpack2(float& lo, float& hi, unsigned long long v) {
    unsigned int a, b;
    asm("mov.b64 {%0, %1}, %2;" : "=r"(a), "=r"(b) : "l"(v));
    lo = __uint_as_float(a);
    hi = __uint_as_float(b);
}

__device__ __forceinline__ void cp_async16(void* smem_dst, const void* gsrc) {
    unsigned int saddr = (unsigned int)__cvta_generic_to_shared(smem_dst);
    asm volatile("cp.async.cg.shared.global [%0], [%1], 16;" :: "r"(saddr), "l"(gsrc));
}
__device__ __forceinline__ void cp_async_commit() {
    asm volatile("cp.async.commit_group;");
}
template <int N>
__device__ __forceinline__ void cp_async_wait() {
    asm volatile("cp.async.wait_group %0;" :: "n"(N));
}

// ---------------------------------------------------------------------------
// Setup kernel: build column j of U = G28...G1, fold phase (-i)^popc(j).
// ---------------------------------------------------------------------------
__global__ void build_W_kernel(const float* __restrict__ rx_params,
                               const float* __restrict__ random_params,
                               OpsParam ops) {
    __shared__ float2 st[QDIM];
    const int j   = blockIdx.x;
    const int tid = threadIdx.x;   // 0..127

    for (int idx = tid; idx < QDIM; idx += 128)
        st[idx] = make_float2(idx == j ? 1.0f : 0.0f, 0.0f);
    __syncthreads();

    for (int p = 0; p < NGATES; p++) {
        int g = ops.kind[p];
        if (g == 3) {
            int cm = 1 << (7 - ops.wa[p]);
            int tm = 1 << (7 - ops.wb[p]);
            for (int idx = tid; idx < QDIM; idx += 128) {
                if ((idx & cm) && !(idx & tm)) {
                    float2 t0 = st[idx];
                    st[idx] = st[idx | tm];
                    st[idx | tm] = t0;
                }
            }
        } else {
            float theta = (p < NRAND) ? random_params[p] : rx_params[p - NRAND];
            float h = 0.5f * theta;
            float c = cosf(h), s = sinf(h);
            int m  = 1 << (7 - ops.wa[p]);
            int t  = tid;
            int j0 = ((t & ~(m - 1)) << 1) | (t & (m - 1));
            int j1 = j0 | m;
            float2 v0 = st[j0], v1 = st[j1], n0, n1;
            if (g == 0) {          // RX
                n0 = make_float2(c * v0.x + s * v1.y, c * v0.y - s * v1.x);
                n1 = make_float2(c * v1.x + s * v0.y, c * v1.y - s * v0.x);
            } else if (g == 1) {   // RY
                n0 = make_float2(c * v0.x - s * v1.x, c * v0.y - s * v1.y);
                n1 = make_float2(s * v0.x + c * v1.x, s * v0.y + c * v1.y);
            } else {               // RZ
                n0 = make_float2(c * v0.x + s * v0.y, c * v0.y - s * v0.x);
                n1 = make_float2(c * v1.x - s * v1.y, c * v1.y + s * v1.x);
            }
            st[j0] = n0;
            st[j1] = n1;
        }
        __syncthreads();
    }

    int pc = __popc(j) & 3;
    for (int i = tid; i < QDIM; i += 128) {
        float2 v = st[i];
        float re, im;
        if (pc == 0)      { re =  v.x; im =  v.y; }
        else if (pc == 1) { re =  v.y; im = -v.x; }
        else if (pc == 2) { re = -v.x; im = -v.y; }
        else              { re = -v.y; im =  v.x; }
        g_B[j * 512 + 2 * i]     = re;
        g_B[j * 512 + 2 * i + 1] = im;
    }
}

// ---------------------------------------------------------------------------
// Main kernel. Smem: R[256][64] (64KB) + double-buffered B tile 2x[64][256]
// (128KB) = 192KB. GEMM inner loop in packed f32x2 (FFMA2).
// ---------------------------------------------------------------------------
#define SMEM_FLOATS (QDIM * BSAMP + 2 * 64 * 256)

__global__ __launch_bounds__(TPB, 1)
void qsim_kernel(const float* __restrict__ x, float* __restrict__ out) {
    extern __shared__ float sm[];
    float* R = sm;                        // [256][64]
    float* Bbuf[2] = { sm + QDIM * BSAMP, sm + QDIM * BSAMP + 64 * 256 };
    const int tid = threadIdx.x;
    const int b   = blockIdx.x;
    const int smp0 = b * BSAMP;

    // ---- Phase 1: build R (4 threads per sample) ----
    {
        int s = tid >> 2, q = tid & 3;
        const float* xp = x + (size_t)(smp0 + s) * 8;
        float fc[8], fs[8];
#pragma unroll
        for (int w = 0; w < 8; w++) {
            float h = 0.5f * xp[w];
            fc[w] = cosf(h);
            fs[w] = sinf(h);
        }
        float f01 = ((q & 2) ? fs[0] : fc[0]) * ((q & 1) ? fs[1] : fc[1]);
#pragma unroll
        for (int jj = 0; jj < 64; jj++) {
            float r = f01;
            r *= (jj & 32) ? fs[2] : fc[2];
            r *= (jj & 16) ? fs[3] : fc[3];
            r *= (jj &  8) ? fs[4] : fc[4];
            r *= (jj &  4) ? fs[5] : fc[5];
            r *= (jj &  2) ? fs[6] : fc[6];
            r *= (jj &  1) ? fs[7] : fc[7];
            R[(q * 64 + jj) * BSAMP + s] = r;
        }
    }

    const int ty = tid >> 5;   // warp id (m-dim)
    const int tx = tid & 31;   // lane   (n-dim)

    float outacc[8][8];
#pragma unroll
    for (int i = 0; i < 8; i++)
#pragma unroll
        for (int k = 0; k < 8; k++) outacc[i][k] = 0.0f;

    // tile copy: rows kc*64.., cols nc*256.. of g_B into Bbuf[buf]
    auto issue_tile = [&](int nc, int kc, int buf) {
#pragma unroll
        for (int it = 0; it < 16; it++) {
            int f   = tid + it * 256;         // float4 slot 0..4095
            int row = f >> 6, c4 = f & 63;
            cp_async16(Bbuf[buf] + row * 256 + c4 * 4,
                       g_B + (size_t)(kc * 64 + row) * 512 + nc * 256 + c4 * 4);
        }
        cp_async_commit();
    };

    for (int nc = 0; nc < 2; nc++) {          // two 256-col chunks of 512
        unsigned long long acc2[2][2][4][2];
#pragma unroll
        for (int a0 = 0; a0 < 2; a0++)
#pragma unroll
            for (int a1 = 0; a1 < 2; a1++)
#pragma unroll
                for (int a2 = 0; a2 < 4; a2++)
#pragma unroll
                    for (int a3 = 0; a3 < 2; a3++) acc2[a0][a1][a2][a3] = 0ULL;

        issue_tile(nc, 0, 0);                 // preload kc=0

        for (int kc = 0; kc < 4; kc++) {      // four 64-row K chunks
            if (kc < 3) {
                issue_tile(nc, kc + 1, (kc + 1) & 1);   // prefetch next
                cp_async_wait<1>();                     // tile kc ready
            } else {
                cp_async_wait<0>();
            }
            __syncthreads();                  // (also covers R on first pass)

            const float* Bs = Bbuf[kc & 1];
#pragma unroll 8
            for (int kk = 0; kk < 64; kk++) {
                const float* Rrow = R + (kc * 64 + kk) * BSAMP;
                float4 a0 = *(const float4*)(Rrow + ty * 4);
                float4 a1 = *(const float4*)(Rrow + 32 + ty * 4);
                const float* Brow = Bs + kk * 256;
                ulonglong2 b0 = *(const ulonglong2*)(Brow + tx * 4);
                ulonglong2 b1 = *(const ulonglong2*)(Brow + 128 + tx * 4);
                unsigned long long A2[2][4] = {
                    { dup2(a0.x), dup2(a0.y), dup2(a0.z), dup2(a0.w) },
                    { dup2(a1.x), dup2(a1.y), dup2(a1.z), dup2(a1.w) } };
                unsigned long long Bv[2][2] = { { b0.x, b0.y }, { b1.x, b1.y } };
#pragma unroll
                for (int mh = 0; mh < 2; mh++)
#pragma unroll
                    for (int nh = 0; nh < 2; nh++)
#pragma unroll
                        for (int mi = 0; mi < 4; mi++)
#pragma unroll
                            for (int np = 0; np < 2; np++)
                                ffma2(acc2[mh][nh][mi][np], A2[mh][mi], Bv[nh][np]);
            }
            __syncthreads();
        }

        // ---- fold |phi|^2 into signed accumulators ----
        // complex amplitude i = nc*128 + nh*64 + tx*2 + {0,1}
        // bit7=nc (k=0), bit6=nh (k=1), bits5..1 = tx (k=2..6), bit0 (k=7)
#pragma unroll
        for (int mh = 0; mh < 2; mh++)
#pragma unroll
            for (int nh = 0; nh < 2; nh++)
#pragma unroll
                for (int mi = 0; mi < 4; mi++) {
                    float cx, cy, cz, cw;
                    unpack2(cx, cy, acc2[mh][nh][mi][0]);   // re,im of i (even)
                    unpack2(cz, cw, acc2[mh][nh][mi][1]);   // re,im of i+1 (odd)
                    float p0 = cx * cx + cy * cy;
                    float p1 = cz * cz + cw * cw;
                    float P = p0 + p1, Q = p0 - p1;
                    int mloc = mh * 4 + mi;
                    outacc[mloc][0] += nc ? -P : P;
                    outacc[mloc][1] += nh ? -P : P;
                    outacc[mloc][7] += Q;
#pragma unroll
                    for (int k = 2; k <= 6; k++)
                        outacc[mloc][k] += ((tx >> (6 - k)) & 1) ? -P : P;
                }
    }

    // ---- warp reduction over tx, store ----
#pragma unroll
    for (int mloc = 0; mloc < 8; mloc++) {
#pragma unroll
        for (int k = 0; k < 8; k++) {
            float v = outacc[mloc][k];
            v += __shfl_xor_sync(0xffffffffu, v, 16);
            v += __shfl_xor_sync(0xffffffffu, v, 8);
            v += __shfl_xor_sync(0xffffffffu, v, 4);
            v += __shfl_xor_sync(0xffffffffu, v, 2);
            v += __shfl_xor_sync(0xffffffffu, v, 1);
            if (tx == 0) {
                int m = (mloc >> 2) * 32 + ty * 4 + (mloc & 3);
                out[(size_t)(smp0 + m) * 8 + k] = v;
            }
        }
    }
}

// ---------------------------------------------------------------------------
// GATE_OPS via the exact reference mechanism (numpy subprocess). PASSED R4.
// ---------------------------------------------------------------------------
static const char* PY_SNIPPET =
    "import numpy as np\n"
    "r = np.random.default_rng(42)\n"
    "for _ in range(20):\n"
    "    g = int(r.integers(0, 4))\n"
    "    if g == 3:\n"
    "        c, t = r.choice(8, size=2, replace=False)\n"
    "        print(3, int(c), int(t))\n"
    "    else:\n"
    "        print(g, int(r.integers(0, 8)), -1)\n";

static bool compute_gate_ops_python(OpsParam& ops, const char* interp) {
    char cmd[2048];
    snprintf(cmd, sizeof(cmd), "%s -c '%s' 2>/dev/null", interp, PY_SNIPPET);
    FILE* f = popen(cmd, "r");
    if (!f) return false;
    int n = 0;
    while (n < NRAND) {
        int g, a, b;
        if (fscanf(f, "%d %d %d", &g, &a, &b) != 3) break;
        if (g < 0 || g > 3 || a < 0 || a > 7 || (g == 3 && (b < 0 || b > 7))) break;
        ops.kind[n] = g; ops.wa[n] = a; ops.wb[n] = b;
        n++;
    }
    pclose(f);
    return n == NRAND;
}

// ---------------------------------------------------------------------------
// Fallback: host-side replication of np.random.default_rng(42).
// ---------------------------------------------------------------------------
namespace nprng {

struct PCG64 { __uint128_t state, inc; int has32; uint32_t buf32; };

static const __uint128_t PCG_MULT =
    (((__uint128_t)2549297995355413924ULL) << 64) | 4865540595714422341ULL;

static uint64_t next64(PCG64& r) {
    r.state = r.state * PCG_MULT + r.inc;
    uint64_t hi = (uint64_t)(r.state >> 64), lo = (uint64_t)r.state;
    uint64_t xv = hi ^ lo;
    unsigned rot = (unsigned)(r.state >> 122);
    return (xv >> rot) | (xv << ((64u - rot) & 63u));
}
static uint32_t next32(PCG64& r) {
    if (r.has32) { r.has32 = 0; return r.buf32; }
    uint64_t v = next64(r);
    r.has32 = 1;
    r.buf32 = (uint32_t)(v >> 32);
    return (uint32_t)v;
}
static void seedseq42(uint64_t out[4]) {
    const uint32_t XSH = 16;
    uint32_t pool[4];
    uint32_t hc = 0x43b0d7e5u;
    auto hashmix = [&](uint32_t v) {
        v ^= hc; hc *= 0x931e8875u; v *= hc; v ^= v >> XSH; return v;
    };
    auto mixf = [&](uint32_t xx, uint32_t yy) {
        uint32_t rr = (xx * 0xca01f9ddu) ^ (yy * 0x4973f715u);
        rr ^= rr >> XSH; return rr;
    };
    pool[0] = hashmix(42u);
    pool[1] = hashmix(0u);
    pool[2] = hashmix(0u);
    pool[3] = hashmix(0u);
    for (int src = 0; src < 4; src++)
        for (int dst = 0; dst < 4; dst++)
            if (src != dst) pool[dst] = mixf(pool[dst], hashmix(pool[src]));
    uint32_t hb = 0x8b51f9ddu;
    uint32_t w[8];
    for (int i = 0; i < 8; i++) {
        uint32_t v = pool[i & 3];
        v ^= hb; hb *= 0x58f38dedu; v *= hb; v ^= v >> XSH;
        w[i] = v;
    }
    for (int k = 0; k < 4; k++)
        out[k] = (uint64_t)w[2 * k] | ((uint64_t)w[2 * k + 1] << 32);
}
static void init42(PCG64& r) {
    uint64_t s4[4];
    seedseq42(s4);
    __uint128_t initstate = (((__uint128_t)s4[0]) << 64) | s4[1];
    __uint128_t initseq   = (((__uint128_t)s4[2]) << 64) | s4[3];
    r.state = 0;
    r.inc   = (initseq << 1) | 1;
    r.state = r.state * PCG_MULT + r.inc;
    r.state += initstate;
    r.state = r.state * PCG_MULT + r.inc;
    r.has32 = 0;
    r.buf32 = 0;
}
static uint64_t lemire32(PCG64& r, uint32_t rng) {
    uint32_t rng_excl = rng + 1;
    uint64_t m = (uint64_t)next32(r) * (uint64_t)rng_excl;
    uint32_t leftover = (uint32_t)m;
    if (leftover < rng_excl) {
        uint32_t threshold = (uint32_t)((0xFFFFFFFFu - rng) % rng_excl);
        while (leftover < threshold) {
            m = (uint64_t)next32(r) * (uint64_t)rng_excl;
            leftover = (uint32_t)m;
        }
    }
    return (uint64_t)(m >> 32);
}
} // namespace nprng

static void compute_gate_ops_cpp(OpsParam& ops) {
    nprng::PCG64 r;
    nprng::init42(r);
    for (int p = 0; p < NRAND; p++) {
        int g = (int)nprng::lemire32(r, 3);
        if (g == 3) {
            uint64_t v6 = nprng::lemire32(r, 6);
            uint64_t v7 = nprng::lemire32(r, 7);
            uint64_t i0 = v6;
            uint64_t i1 = (v7 == v6) ? 7 : v7;
            uint64_t js = nprng::lemire32(r, 1);
            if (js == 0) { uint64_t t = i0; i0 = i1; i1 = t; }
            ops.kind[p] = 3;
            ops.wa[p] = (int)i0;
            ops.wb[p] = (int)i1;
        } else {
            ops.kind[p] = g;
            ops.wa[p] = (int)nprng::lemire32(r, 7);
            ops.wb[p] = -1;
        }
    }
}

extern "C" void kernel_launch(void* const* d_in, const int* in_sizes, int n_in,
                              void* d_out, int out_size) {
    const float* x  = nullptr;
    const float* rx = nullptr;
    const float* rp = nullptr;
    for (int i = 0; i < n_in; i++) {
        if (in_sizes[i] == 8)       rx = (const float*)d_in[i];
        else if (in_sizes[i] == 20) rp = (const float*)d_in[i];
        else                        x  = (const float*)d_in[i];
    }
    if (!x)  x  = (const float*)d_in[0];
    if (!rx) rx = (const float*)d_in[1];
    if (!rp) rp = (const float*)d_in[2];
    float* out = (float*)d_out;
    (void)out_size;

    OpsParam ops;
    bool ok = compute_gate_ops_python(ops, "python3");
    if (!ok) ok = compute_gate_ops_python(ops, "python");
    if (!ok) {
        fprintf(stderr, "[qsim] python GATE_OPS derivation FAILED -> C++ fallback\n");
        compute_gate_ops_cpp(ops);
    }

    for (int w = 0; w < 8; w++) {   // final RX layer
        ops.kind[NRAND + w] = 0;
        ops.wa[NRAND + w] = w;
        ops.wb[NRAND + w] = -1;
    }

    cudaFuncSetAttribute(qsim_kernel, cudaFuncAttributeMaxDynamicSharedMemorySize,
                         SMEM_FLOATS * sizeof(float));

    build_W_kernel<<<QDIM, 128>>>(rx, rp, ops);
    qsim_kernel<<<NSAMP / BSAMP, TPB, SMEM_FLOATS * sizeof(float)>>>(x, out);
}